// round 3
// baseline (speedup 1.0000x reference)
#include <cuda_runtime.h>

// Problem constants (fixed by setup_inputs)
#define BB      4
#define IN_DIM  8
#define OUT_DIM 64
#define N_WIN   64
#define N_SEQ   4096
#define N_REAL  6144

typedef unsigned long long ull;

// Scratch: z duplicated pairs (z,z), and weight pairs (W[o],W[o+32]), lane-fastest
__device__ float2 g_zdup[BB * IN_DIM * N_REAL];      // 1.5 MB
__device__ float2 g_wpair[IN_DIM * N_WIN * 32];      // 128 KB

// ---------------- fused prep kernel ----------------
// Blocks [0, 96):   build g_zdup via binary search (no separate zero pass)
// Blocks [96, 160): build g_wpair transpose

#define Z_ELEMS (BB * N_REAL)            // 24576
#define W_ELEMS (IN_DIM * N_WIN * 32)    // 16384

__global__ void prep_kernel(const float* __restrict__ x,
                            const float* __restrict__ w,
                            const int*   __restrict__ srcIdx) {
    int g = blockIdx.x * 256 + threadIdx.x;
    if (g < Z_ELEMS) {
        int b = g / N_REAL, t = g % N_REAL;
        const int* row = srcIdx + b * N_SEQ;
        // binary search: is t present in sorted-unique row?
        int lo = 0, hi = N_SEQ - 1, pos = -1;
        while (lo <= hi) {
            int mid = (lo + hi) >> 1;
            int v = row[mid];
            if (v == t) { pos = mid; break; }
            if (v < t) lo = mid + 1; else hi = mid - 1;
        }
#pragma unroll
        for (int i = 0; i < IN_DIM; i++) {
            float v = (pos >= 0) ? x[(b * IN_DIM + i) * N_SEQ + pos] : 0.f;
            g_zdup[(b * IN_DIM + i) * N_REAL + t] = make_float2(v, v);
        }
    } else {
        int h = g - Z_ELEMS;
        if (h < W_ELEMS) {
            int lane = h & 31;
            int wi   = (h >> 5) & (N_WIN - 1);
            int i    = h >> 11;
            float a = w[(lane)      * IN_DIM * N_WIN + i * N_WIN + wi];
            float c = w[(lane + 32) * IN_DIM * N_WIN + i * N_WIN + wi];
            g_wpair[h] = make_float2(a, c);
        }
    }
}

// ---------------- main conv kernel ----------------

__device__ __forceinline__ ull ffma2(ull a, ull b, ull c) {
    ull d;
    asm("fma.rn.f32x2 %0, %1, %2, %3;" : "=l"(d) : "l"(a), "l"(b), "l"(c));
    return d;
}

__device__ __forceinline__ ull pack2(float x, float y) {
    ull r;
    asm("mov.b64 %0, {%1, %2};" : "=l"(r) : "f"(x), "f"(y));
    return r;
}

__device__ __forceinline__ void unpack2(ull v, float& x, float& y) {
    asm("mov.b64 {%0, %1}, %2;" : "=f"(x), "=f"(y) : "l"(v));
}

#define T_BLK   64    // t-tile per block
#define THREADS 128   // 4 warps, each warp owns 16 t

__global__ __launch_bounds__(THREADS, 4)
void conv_kernel(const float* __restrict__ bias, float* __restrict__ out) {
    __shared__ __align__(16) ull zs[IN_DIM * 128];   // z tile (dup pairs), local t = t0-63+k
    __shared__ float outtile[OUT_DIM * 65];          // padded transpose buffer

    const int tid  = threadIdx.x;
    const int b    = blockIdx.x / (N_REAL / T_BLK);
    const int tile = blockIdx.x % (N_REAL / T_BLK);
    const int t0   = tile * T_BLK;

    // Stage z tile: 1024 entries, 8 per thread, coalesced
    const ull* zg = (const ull*)g_zdup;
#pragma unroll
    for (int p = 0; p < 8; p++) {
        int idx = tid + p * THREADS;          // 0..1023 = 8 rows x 128
        int i = idx >> 7;
        int k = idx & 127;
        int t = t0 - 63 + k;
        ull v = 0ULL;
        if (t >= 0 && t < N_REAL) v = zg[(b * IN_DIM + i) * N_REAL + t];
        zs[idx] = v;
    }
    __syncthreads();

    const int wid  = tid >> 5;                // warp owns t in [t0+16*wid, t0+16*wid+16)
    const int lane = tid & 31;                // lane owns channel pair (lane, lane+32)

    ull acc[16];
    {
        ull bpack = pack2(bias[lane], bias[lane + 32]);
#pragma unroll
        for (int j = 0; j < 16; j++) acc[j] = bpack;
    }

    const ull* wbase = (const ull*)g_wpair + lane;

#pragma unroll 1
    for (int i = 0; i < IN_DIM; i++) {
        const ull* zrow = zs + i * 128 + (16 * wid + 56);
        const ull* wrow = wbase + i * (N_WIN * 32);

#pragma unroll 1
        for (int w0 = 0; w0 < N_WIN; w0 += 8) {
            // z window: 24 dup-pairs covering lags [w0,w0+8) for 16 outputs
            ull zw[24];
            const ulonglong2* zp = (const ulonglong2*)(zrow - w0);  // 16B aligned
#pragma unroll
            for (int k2 = 0; k2 < 12; k2++) {
                ulonglong2 v = zp[k2];
                zw[2 * k2]     = v.x;
                zw[2 * k2 + 1] = v.y;
            }
            // 8 weight pairs: warp-coalesced LDG.64 (256B = 2 lines each)
            ull wt[8];
#pragma unroll
            for (int w = 0; w < 8; w++) wt[w] = wrow[(w0 + w) * 32];

#pragma unroll
            for (int w = 0; w < 8; w++) {
#pragma unroll
                for (int j = 0; j < 16; j++) {
                    // zw[j+7-w] == z[(t0 + 16*wid + j) - (w0 + w)]
                    acc[j] = ffma2(zw[j + 7 - w], wt[w], acc[j]);
                }
            }
        }
    }

    // Transpose through smem (stride 65 -> conflict-free STS)
#pragma unroll
    for (int j = 0; j < 16; j++) {
        float lo, hi;
        unpack2(acc[j], lo, hi);
        int lt = 16 * wid + j;
        outtile[lane * 65 + lt]        = lo;
        outtile[(lane + 32) * 65 + lt] = hi;
    }
    __syncthreads();

    // Vectorized coalesced stores: 1024 float4 quads, 8 per thread
#pragma unroll
    for (int r = 0; r < 8; r++) {
        int q  = tid + r * THREADS;           // 0..1023
        int o  = q >> 4;
        int tq = q & 15;
        float4 v;
        v.x = outtile[o * 65 + 4 * tq + 0];
        v.y = outtile[o * 65 + 4 * tq + 1];
        v.z = outtile[o * 65 + 4 * tq + 2];
        v.w = outtile[o * 65 + 4 * tq + 3];
        *reinterpret_cast<float4*>(out + (b * OUT_DIM + o) * N_REAL + t0 + 4 * tq) = v;
    }
}

// ---------------- launch ----------------

extern "C" void kernel_launch(void* const* d_in, const int* in_sizes, int n_in,
                              void* d_out, int out_size) {
    const float* x      = (const float*)d_in[0];   // (4, 8, 4096)
    const float* weight = (const float*)d_in[1];   // (64, 8, 64)
    const float* bias   = (const float*)d_in[2];   // (64,)
    const int*   srcIdx = (const int*)d_in[3];     // (4, 4096)
    float*       out    = (float*)d_out;           // (4, 64, 6144)

    int prep_blocks = (Z_ELEMS + W_ELEMS + 255) / 256;   // 160
    prep_kernel<<<prep_blocks, 256>>>(x, weight, srcIdx);
    conv_kernel<<<BB * (N_REAL / T_BLK), THREADS>>>(bias, out);
}

// round 4
// speedup vs baseline: 1.8260x; 1.8260x over previous
#include <cuda_runtime.h>

// Problem constants (fixed by setup_inputs)
#define BB      4
#define IN_DIM  8
#define OUT_DIM 64
#define N_WIN   64
#define N_SEQ   4096
#define N_REAL  6144

typedef unsigned long long ull;

// Transposed weights: g_wt[i][w][o]  (128 KB, L1-resident in conv kernel)
__device__ float g_wt[IN_DIM * N_WIN * OUT_DIM];

// ---------------- prep: weight transpose only ----------------

__global__ void wprep_kernel(const float* __restrict__ w) {
    int g = blockIdx.x * 256 + threadIdx.x;      // 16384 = 64 o x 512 iw
    int o  = g >> 9;
    int iw = g & 511;
    float v = w[o * 512 + iw];                   // coalesced read (iw fastest)
    g_wt[iw * OUT_DIM + o] = v;                  // scattered write (128KB once, cheap)
}

// ---------------- main conv kernel ----------------

__device__ __forceinline__ ull ffma2(ull a, ull b, ull c) {
    ull d;
    asm("fma.rn.f32x2 %0, %1, %2, %3;" : "=l"(d) : "l"(a), "l"(b), "l"(c));
    return d;
}

__device__ __forceinline__ ull pack2(float x, float y) {
    ull r;
    asm("mov.b64 %0, {%1, %2};" : "=l"(r) : "f"(x), "f"(y));
    return r;
}

__device__ __forceinline__ void unpack2(ull v, float& x, float& y) {
    asm("mov.b64 {%0, %1}, %2;" : "=f"(x), "=f"(y) : "l"(v));
}

#define T_BLK   64
#define THREADS 256
#define NTILES  (N_REAL / T_BLK)   // 96

__global__ __launch_bounds__(THREADS, 3)
void conv_kernel(const float* __restrict__ x,
                 const int*   __restrict__ srcIdx,
                 const float* __restrict__ bias,
                 float*       __restrict__ out) {
    __shared__ float zraw[IN_DIM][128];                    // z[t0-63 .. t0+64], 4KB
    __shared__ __align__(16) ull zs8[IN_DIM][128];         // (z[k], z[k+8]) pairs, 8KB
    __shared__ float outtile[OUT_DIM * (T_BLK + 1)];       // padded transpose, 16.6KB

    const int tid = threadIdx.x;
    const int b   = blockIdx.x / NTILES;
    const int t0  = (blockIdx.x % NTILES) * T_BLK;

    // ---- stage z directly from x via binary search on sorted-unique sourceIdx ----
#pragma unroll
    for (int p = 0; p < 4; p++) ((float*)zraw)[tid + p * THREADS] = 0.f;
    __syncthreads();

    const int* row = srcIdx + b * N_SEQ;
    const int tlo = t0 - 63, thi = t0 + 63;
    // s_lo: first s with row[s] >= tlo ; s_hi: first s with row[s] > thi
    int lo = 0, hi = N_SEQ;
    while (lo < hi) { int m = (lo + hi) >> 1; if (row[m] < tlo) lo = m + 1; else hi = m; }
    const int s_lo = lo;
    hi = N_SEQ;
    while (lo < hi) { int m = (lo + hi) >> 1; if (row[m] <= thi) lo = m + 1; else hi = m; }
    const int s_hi = lo;

    for (int s = s_lo + tid; s < s_hi; s += THREADS) {
        int tl = row[s] - tlo;                       // in [0, 126]
#pragma unroll
        for (int i = 0; i < IN_DIM; i++)
            zraw[i][tl] = x[(b * IN_DIM + i) * N_SEQ + s];
    }
    __syncthreads();

    // ---- build t-pair table zs8[i][k] = (z[k], z[k+8]) ; only k < 120 used ----
#pragma unroll
    for (int p = 0; p < 4; p++) {
        int e = tid + p * THREADS;                   // 0..1023
        int i = e >> 7, k = e & 127;
        if (k < 120) zs8[i][k] = pack2(zraw[i][k], zraw[i][k + 8]);
    }
    __syncthreads();

    // ---- compute: warp -> (t-group tg, o-half oh); lane -> o ----
    const int warp = tid >> 5;
    const int lane = tid & 31;
    const int tg   = warp >> 1;                      // 0..3 : t in [t0+16tg, t0+16tg+16)
    const int oh   = warp & 1;
    const int o    = oh * 32 + lane;

    ull acc[8];                                      // acc[j] = (out[t0+16tg+j], out[..+j+8])
    {
        float bv = bias[o];
        ull bp = pack2(bv, bv);
#pragma unroll
        for (int j = 0; j < 8; j++) acc[j] = bp;
    }

    const int B0 = 56 + 16 * tg;

#pragma unroll 1
    for (int i = 0; i < IN_DIM; i++) {
        const ull*   z8   = zs8[i];
        const float* wrow = g_wt + i * (N_WIN * OUT_DIM) + o;

        // initial 16-pair window for lag chunk c=0 (w in [0,8))
        ull zw[16];
#pragma unroll
        for (int q = 0; q < 8; q++) {
            ulonglong2 v = *reinterpret_cast<const ulonglong2*>(z8 + B0 + 2 * q);
            zw[2 * q] = v.x; zw[2 * q + 1] = v.y;
        }

#pragma unroll
        for (int c = 0; c < 8; c++) {
            // 8 scalar weights (coalesced LDG.32, L1-resident), duplicated into pairs
            ull wd[8];
#pragma unroll
            for (int dw = 0; dw < 8; dw++) {
                float wv = wrow[(8 * c + dw) * OUT_DIM];
                wd[dw] = pack2(wv, wv);
            }
#pragma unroll
            for (int dw = 0; dw < 8; dw++) {
#pragma unroll
                for (int j = 0; j < 8; j++) {
                    // zw[7+j-dw] == (z[t-w], z[t+8-w]) for t=t0+16tg+j, w=8c+dw
                    acc[j] = ffma2(zw[7 + j - dw], wd[dw], acc[j]);
                }
            }
            if (c < 7) {
                // slide window down by 8 lags (register renames under full unroll)
#pragma unroll
                for (int k = 15; k >= 8; k--) zw[k] = zw[k - 8];
                const int Bn = B0 - 8 * (c + 1);
#pragma unroll
                for (int q = 0; q < 4; q++) {
                    ulonglong2 v = *reinterpret_cast<const ulonglong2*>(z8 + Bn + 2 * q);
                    zw[2 * q] = v.x; zw[2 * q + 1] = v.y;
                }
            }
        }
    }

    // ---- transpose through smem (stride 65 -> conflict-free), coalesced STG.128 ----
#pragma unroll
    for (int j = 0; j < 8; j++) {
        float vlo, vhi;
        unpack2(acc[j], vlo, vhi);
        int base = o * (T_BLK + 1) + 16 * tg + j;
        outtile[base]     = vlo;
        outtile[base + 8] = vhi;
    }
    __syncthreads();

#pragma unroll
    for (int r = 0; r < 4; r++) {
        int q  = tid + r * THREADS;                  // 0..1023 float4 quads
        int oo = q >> 4;
        int tq = q & 15;
        const float* src = outtile + oo * (T_BLK + 1) + 4 * tq;
        float4 v;
        v.x = src[0]; v.y = src[1]; v.z = src[2]; v.w = src[3];
        *reinterpret_cast<float4*>(out + (b * OUT_DIM + oo) * N_REAL + t0 + 4 * tq) = v;
    }
}

// ---------------- launch ----------------

extern "C" void kernel_launch(void* const* d_in, const int* in_sizes, int n_in,
                              void* d_out, int out_size) {
    const float* x      = (const float*)d_in[0];   // (4, 8, 4096)
    const float* weight = (const float*)d_in[1];   // (64, 8, 64)
    const float* bias   = (const float*)d_in[2];   // (64,)
    const int*   srcIdx = (const int*)d_in[3];     // (4, 4096)
    float*       out    = (float*)d_out;           // (4, 64, 6144)

    wprep_kernel<<<(IN_DIM * N_WIN * OUT_DIM + 255) / 256, 256>>>(weight);
    conv_kernel<<<BB * NTILES, THREADS>>>(x, srcIdx, bias, out);
}

// round 6
// speedup vs baseline: 1.9790x; 1.0838x over previous
#include <cuda_runtime.h>
#include <cuda_bf16.h>
#include <cstdint>

#define BB      4
#define IN_DIM  8
#define OUT_DIM 64
#define N_WIN   64
#define N_SEQ   4096
#define N_REAL  6144

#define T_TILE  128
#define NTILES  (N_REAL / T_TILE)   // 48
#define THREADS 256

// Prepped weights per i: 64 rows (o) x 128 bf16 cols [whi(0..63) | wlo(64..127)],
// lag axis pre-flipped: col c <-> lag 63-c. 16KB per i.
__device__ __align__(16) unsigned short g_B[IN_DIM][OUT_DIM * 128];

// ---------------- helpers ----------------

// pack {lo16: bf16(z0), hi16: bf16(z1)}
__device__ __forceinline__ uint32_t bfpair(float z0, float z1) {
    uint32_t r;
    asm("cvt.rn.bf16x2.f32 %0, %1, %2;" : "=r"(r) : "f"(z1), "f"(z0));
    return r;
}

__device__ __forceinline__ void hl_split(float z0, float z1, uint32_t& hp, uint32_t& lp) {
    hp = bfpair(z0, z1);
    float h0 = __uint_as_float(hp << 16);
    float h1 = __uint_as_float(hp & 0xffff0000u);
    lp = bfpair(z0 - h0, z1 - h1);
}

__device__ __forceinline__ void mma_bf16(float* d, const uint32_t* a, const uint32_t* b) {
    asm volatile(
        "mma.sync.aligned.m16n8k16.row.col.f32.bf16.bf16.f32 "
        "{%0,%1,%2,%3}, {%4,%5,%6,%7}, {%8,%9}, {%0,%1,%2,%3};"
        : "+f"(d[0]), "+f"(d[1]), "+f"(d[2]), "+f"(d[3])
        : "r"(a[0]), "r"(a[1]), "r"(a[2]), "r"(a[3]), "r"(b[0]), "r"(b[1]));
}

// ---------------- weight prep: hi/lo split + lag flip ----------------

__global__ void wprep(const float* __restrict__ w) {
    int g = blockIdx.x * 256 + threadIdx.x;          // (o, i, wl), wl fastest
    if (g >= OUT_DIM * IN_DIM * N_WIN) return;
    int wl = g & 63;
    int i  = (g >> 6) & 7;
    int o  = g >> 9;
    float f = w[g];
    uint32_t hp, lp;
    hl_split(f, 0.f, hp, lp);                        // lo16 of each = bf16 parts of f
    int c = 63 - wl;                                 // flipped lag
    g_B[i][o * 128 + c]      = (unsigned short)(hp & 0xffff);
    g_B[i][o * 128 + 64 + c] = (unsigned short)(lp & 0xffff);
}

// ---------------- main kernel ----------------
// SMEM: zraw 8x192 f32 @0 (6144B) | bias @6144 (256B) |
//       B tile 64 x 136 halves @6400 (17408B) | A tile 128 x 136 halves @23808 (34816B)
//       outtile 64 x 132 f32 reuses A region.
#define SM_ZRAW 0
#define SM_BIAS 6144
#define SM_B    6400
#define SM_A    23808
#define PITCH32 68        // row pitch in uint32 units (136 halves = 272B)
#define SMEM_TOTAL (23808 + 34816)

__global__ __launch_bounds__(THREADS, 2)
void conv_mma(const float* __restrict__ x, const int* __restrict__ srcIdx,
              const float* __restrict__ bias, float* __restrict__ out) {
    extern __shared__ __align__(16) unsigned char smem[];
    float*    zraw    = (float*)(smem + SM_ZRAW);
    float*    bias_s  = (float*)(smem + SM_BIAS);
    uint32_t* Bs32    = (uint32_t*)(smem + SM_B);
    uint32_t* As32    = (uint32_t*)(smem + SM_A);
    float*    outtile = (float*)(smem + SM_A);       // reuse after compute

    const int tid  = threadIdx.x;
    const int wid  = tid >> 5;
    const int lane = tid & 31;
    const int b    = blockIdx.x / NTILES;
    const int t0   = (blockIdx.x % NTILES) * T_TILE;

    // ---- stage z window [t0-63, t0+127] via binary search on sorted-unique sourceIdx ----
    if (tid < OUT_DIM) bias_s[tid] = bias[tid];
#pragma unroll
    for (int p = 0; p < 6; p++) zraw[tid + p * THREADS] = 0.f;
    __syncthreads();

    const int* rowp = srcIdx + b * N_SEQ;
    const int tlo = t0 - 63, thi = t0 + 127;
    int lo = 0, hi = N_SEQ;
    while (lo < hi) { int m = (lo + hi) >> 1; if (rowp[m] < tlo) lo = m + 1; else hi = m; }
    const int s_lo = lo;
    hi = N_SEQ;
    while (lo < hi) { int m = (lo + hi) >> 1; if (rowp[m] <= thi) lo = m + 1; else hi = m; }
    const int s_hi = lo;
    for (int s = s_lo + tid; s < s_hi; s += THREADS) {
        int tl = rowp[s] - tlo;                      // in [0, 190]
#pragma unroll
        for (int i = 0; i < IN_DIM; i++)
            zraw[i * 192 + tl] = x[(b * IN_DIM + i) * N_SEQ + s];
    }
    __syncthreads();

    // warp fragment geometry (mma m16n8k16)
    const int rowA = (wid << 4) + (lane >> 2);       // warp owns t rows [16*wid, 16*wid+16)
    const int colp = lane & 3;                       // k-pair index within 8-wide k chunk
    const int rowg = lane >> 2;

    float acc[8][4];
#pragma unroll
    for (int n = 0; n < 8; n++)
#pragma unroll
        for (int q = 0; q < 4; q++) acc[n][q] = 0.f;

#pragma unroll 1
    for (int i = 0; i < IN_DIM; i++) {
        // ---- build A tile: A[r][c] = zwin[r + c], hi cols 0..63, lo cols 64..127 ----
        {
            const float* zi = zraw + i * 192;
            int r = tid >> 1, half = tid & 1;
            const float* zr = zi + r + 32 * half;
            uint32_t* dst = As32 + r * PITCH32 + 16 * half;
#pragma unroll
            for (int p = 0; p < 16; p++) {
                uint32_t hp, lp;
                hl_split(zr[2 * p], zr[2 * p + 1], hp, lp);
                dst[p]      = hp;
                dst[p + 32] = lp;
            }
        }
        // ---- copy prepped B image into padded smem ----
        {
            const uint4* gb = (const uint4*)g_B[i];
#pragma unroll
            for (int j = 0; j < 4; j++) {
                int u = tid + j * THREADS;           // 0..1023
                int o = u >> 4, q = u & 15;
                *(uint4*)(Bs32 + o * PITCH32 + q * 4) = gb[u];
            }
        }
        __syncthreads();

        // ---- MMA over K=64 (4 chunks of 16), 3 hi/lo terms ----
#pragma unroll
        for (int kc = 0; kc < 4; kc++) {
            const int k0h = kc * 8;                  // uint32 col offset of k-chunk
            const uint32_t* Ap = As32 + rowA * PITCH32 + colp;
            uint32_t ah[4], al[4];
            ah[0] = Ap[k0h];                ah[1] = Ap[8 * PITCH32 + k0h];
            ah[2] = Ap[k0h + 4];            ah[3] = Ap[8 * PITCH32 + k0h + 4];
            al[0] = Ap[k0h + 32];           al[1] = Ap[8 * PITCH32 + k0h + 32];
            al[2] = Ap[k0h + 36];           al[3] = Ap[8 * PITCH32 + k0h + 36];
#pragma unroll
            for (int n = 0; n < 8; n++) {
                const uint32_t* Bp = Bs32 + (n * 8 + rowg) * PITCH32 + colp;
                uint32_t bh[2], bl[2];
                bh[0] = Bp[k0h];      bh[1] = Bp[k0h + 4];
                bl[0] = Bp[k0h + 32]; bl[1] = Bp[k0h + 36];
                mma_bf16(acc[n], ah, bh);            // zhi * whi
                mma_bf16(acc[n], ah, bl);            // zhi * wlo
                mma_bf16(acc[n], al, bh);            // zlo * whi
            }
        }
        __syncthreads();                             // operands consumed -> safe to rebuild
    }

    // ---- epilogue: D[t][o] + bias -> outtile[o][t] (pitch 132, conflict-free) ----
    {
        const int tr0 = rowA;
        const int oc  = 2 * colp;
#pragma unroll
        for (int n = 0; n < 8; n++) {
            int o0 = n * 8 + oc;
            outtile[o0 * 132 + tr0]           = acc[n][0] + bias_s[o0];
            outtile[(o0 + 1) * 132 + tr0]     = acc[n][1] + bias_s[o0 + 1];
            outtile[o0 * 132 + tr0 + 8]       = acc[n][2] + bias_s[o0];
            outtile[(o0 + 1) * 132 + tr0 + 8] = acc[n][3] + bias_s[o0 + 1];
        }
    }
    __syncthreads();

    // ---- coalesced STG.128: 2048 float4 quads, 8 per thread ----
#pragma unroll
    for (int r2 = 0; r2 < 8; r2++) {
        int q  = tid + r2 * THREADS;                 // 0..2047
        int o  = q >> 5;
        int tq = q & 31;
        float4 v = *(float4*)(outtile + o * 132 + 4 * tq);
        *(float4*)(out + (b * OUT_DIM + o) * N_REAL + t0 + 4 * tq) = v;
    }
}

// ---------------- launch ----------------

extern "C" void kernel_launch(void* const* d_in, const int* in_sizes, int n_in,
                              void* d_out, int out_size) {
    const float* x      = (const float*)d_in[0];   // (4, 8, 4096)
    const float* weight = (const float*)d_in[1];   // (64, 8, 64)
    const float* bias   = (const float*)d_in[2];   // (64,)
    const int*   srcIdx = (const int*)d_in[3];     // (4, 4096)
    float*       out    = (float*)d_out;           // (4, 64, 6144)

    static bool attr_done = false;
    if (!attr_done) {
        cudaFuncSetAttribute(conv_mma, cudaFuncAttributeMaxDynamicSharedMemorySize, SMEM_TOTAL);
        attr_done = true;
    }

    wprep<<<(OUT_DIM * IN_DIM * N_WIN + 255) / 256, 256>>>(weight);
    conv_mma<<<BB * NTILES, THREADS, SMEM_TOTAL>>>(x, srcIdx, bias, out);
}

// round 7
// speedup vs baseline: 2.3615x; 1.1933x over previous
#include <cuda_runtime.h>
#include <cuda_bf16.h>
#include <cstdint>

#define BB      4
#define IN_DIM  8
#define OUT_DIM 64
#define N_WIN   64
#define N_SEQ   4096
#define N_REAL  6144

#define T_TILE  64
#define NTILES  (N_REAL / T_TILE)   // 96
#define THREADS 256

// Prepped weights per i: 64 rows (o) x 128 bf16 cols [whi(0..63) | wlo(64..127)],
// lag pre-flipped: col c <-> lag 63-c. 16KB per i.
__device__ __align__(16) unsigned short g_B[IN_DIM][OUT_DIM * 128];

// ---------------- helpers ----------------

__device__ __forceinline__ uint32_t smem_u32(const void* p) {
    uint32_t a;
    asm("{ .reg .u64 t; cvta.to.shared.u64 t, %1; cvt.u32.u64 %0, t; }" : "=r"(a) : "l"(p));
    return a;
}

// pack {lo16: bf16(z0), hi16: bf16(z1)}
__device__ __forceinline__ uint32_t bfpair(float z0, float z1) {
    uint32_t r;
    asm("cvt.rn.bf16x2.f32 %0, %1, %2;" : "=r"(r) : "f"(z1), "f"(z0));
    return r;
}

__device__ __forceinline__ void hl_split(float z0, float z1, uint32_t& hp, uint32_t& lp) {
    hp = bfpair(z0, z1);
    float h0 = __uint_as_float(hp << 16);
    float h1 = __uint_as_float(hp & 0xffff0000u);
    lp = bfpair(z0 - h0, z1 - h1);
}

__device__ __forceinline__ void mma_bf16(float* d, const uint32_t* a, const uint32_t* b) {
    asm volatile(
        "mma.sync.aligned.m16n8k16.row.col.f32.bf16.bf16.f32 "
        "{%0,%1,%2,%3}, {%4,%5,%6,%7}, {%8,%9}, {%0,%1,%2,%3};"
        : "+f"(d[0]), "+f"(d[1]), "+f"(d[2]), "+f"(d[3])
        : "r"(a[0]), "r"(a[1]), "r"(a[2]), "r"(a[3]), "r"(b[0]), "r"(b[1]));
}

__device__ __forceinline__ void ldmx4(uint32_t* r, uint32_t addr) {
    asm volatile("ldmatrix.sync.aligned.m8n8.x4.shared.b16 {%0,%1,%2,%3}, [%4];"
                 : "=r"(r[0]), "=r"(r[1]), "=r"(r[2]), "=r"(r[3]) : "r"(addr));
}

__device__ __forceinline__ void cpasync16(uint32_t dst, const void* src) {
    asm volatile("cp.async.ca.shared.global [%0], [%1], 16;" :: "r"(dst), "l"(src));
}
#define CP_COMMIT() asm volatile("cp.async.commit_group;" ::: "memory")
#define CP_WAIT0()  asm volatile("cp.async.wait_group 0;" ::: "memory")

// ---------------- weight prep: hi/lo split + lag flip ----------------

__global__ void wprep(const float* __restrict__ w) {
    int g = blockIdx.x * 256 + threadIdx.x;          // (o, i, wl), wl fastest
    if (g >= OUT_DIM * IN_DIM * N_WIN) return;
    int wl = g & 63;
    int i  = (g >> 6) & 7;
    int o  = g >> 9;
    float f = w[g];
    uint32_t hp, lp;
    hl_split(f, 0.f, hp, lp);
    int c = 63 - wl;
    g_B[i][o * 128 + c]      = (unsigned short)(hp & 0xffff);
    g_B[i][o * 128 + 64 + c] = (unsigned short)(lp & 0xffff);
}

// ---------------- main kernel ----------------
// SMEM (bytes): zraw 8x128 f32 @0 | bias @4096 | B bufs 2x17408 @4352 | A bufs 2x17408 @39168
// outtile (64x68 f32 = 17408) reuses A region after compute.
#define SM_ZRAW 0
#define SM_BIAS 4096
#define SM_B    4352
#define SM_A    39168
#define BUF_SZ  17408      // 64 rows x 68 words x 4B
#define PITCHW  68         // row pitch in 32-bit words (272B; 4r mod 32 banks -> conflict-free)
#define SMEM_TOTAL (SM_A + 2 * BUF_SZ)   // 73984

__global__ __launch_bounds__(THREADS, 3)
void conv_mma(const float* __restrict__ x, const int* __restrict__ srcIdx,
              const float* __restrict__ bias, float* __restrict__ out) {
    extern __shared__ __align__(16) unsigned char smem[];
    float* zraw    = (float*)(smem + SM_ZRAW);
    float* bias_s  = (float*)(smem + SM_BIAS);
    float* outtile = (float*)(smem + SM_A);
    const uint32_t sb = smem_u32(smem);

    const int tid  = threadIdx.x;
    const int wid  = tid >> 5;
    const int lane = tid & 31;
    const int b    = blockIdx.x / NTILES;
    const int t0   = (blockIdx.x % NTILES) * T_TILE;

    if (tid < OUT_DIM) bias_s[tid] = bias[tid];
#pragma unroll
    for (int p = 0; p < 4; p++) zraw[tid + p * THREADS] = 0.f;
    __syncthreads();

    // ---- stage z window [t0-63, t0+63] via binary search on sorted-unique sourceIdx ----
    const int* rowp = srcIdx + b * N_SEQ;
    const int tlo = t0 - 63, thi = t0 + 63;
    int lo = 0, hi = N_SEQ;
    while (lo < hi) { int m = (lo + hi) >> 1; if (rowp[m] < tlo) lo = m + 1; else hi = m; }
    const int s_lo = lo;
    hi = N_SEQ;
    while (lo < hi) { int m = (lo + hi) >> 1; if (rowp[m] <= thi) lo = m + 1; else hi = m; }
    const int s_hi = lo;
    for (int s = s_lo + tid; s < s_hi; s += THREADS) {
        int tl = rowp[s] - tlo;                      // [0, 126]
#pragma unroll
        for (int i = 0; i < IN_DIM; i++)
            zraw[i * 128 + tl] = x[(b * IN_DIM + i) * N_SEQ + s];
    }

    // warp tiling: 4 m-tiles x 2 n-halves
    const int mb = wid & 3;                          // m16 tile: t rows [16mb, 16mb+16)
    const int nb = wid >> 2;                         // n32 half: o in [32nb, 32nb+32)

    // ldmatrix lane address offsets (bytes, within a buffer)
    const uint32_t a_off =
        ((16 * mb + (lane & 7) + 8 * ((lane >> 3) & 1)) * PITCHW + 4 * (lane >> 4)) * 4;
    const uint32_t b_off =
        (((lane & 7) + 8 * (lane >> 4)) * PITCHW + 4 * ((lane >> 3) & 1)) * 4
        + nb * (32 * PITCHW * 4);

    float acc[4][4];
#pragma unroll
    for (int c = 0; c < 4; c++)
#pragma unroll
        for (int q = 0; q < 4; q++) acc[c][q] = 0.f;

    // ---- build A tile for iteration i into buffer buf ----
    auto build_A = [&](int i, int buf) {
        const float* zi = zraw + i * 128;
        int r = tid >> 2, qtr = tid & 3;             // row r, col-quarter qtr
        const float* zr = zi + r + 16 * qtr;         // A[r][c] = zwin[r+c]
        uint32_t* dst = (uint32_t*)(smem + SM_A + buf * BUF_SZ) + r * PITCHW + 8 * qtr;
#pragma unroll
        for (int p = 0; p < 8; p++) {
            uint32_t hp, lp;
            hl_split(zr[2 * p], zr[2 * p + 1], hp, lp);
            dst[p]      = hp;                        // hi cols (words 0..31)
            dst[p + 32] = lp;                        // lo cols (words 32..63)
        }
    };
    // ---- async-copy B image for iteration i into buffer buf ----
    auto copy_B = [&](int i, int buf) {
        const uint4* gb = (const uint4*)g_B[i];
        uint32_t dbase = sb + SM_B + buf * BUF_SZ;
#pragma unroll
        for (int k2 = 0; k2 < 4; k2++) {
            int u = tid + k2 * THREADS;              // 0..1023
            int o = u >> 4, q = u & 15;
            cpasync16(dbase + (o * PITCHW + 4 * q) * 4, gb + u);
        }
        CP_COMMIT();
    };

    __syncthreads();                                 // zraw ready
    copy_B(0, 0);
    build_A(0, 0);
    CP_WAIT0();
    __syncthreads();

#pragma unroll 1
    for (int i = 0; i < IN_DIM; i++) {
        const int buf = i & 1;
        if (i < IN_DIM - 1) copy_B(i + 1, buf ^ 1);  // overlaps with MMA below

        const uint32_t sbA = sb + SM_A + buf * BUF_SZ;
        const uint32_t sbB = sb + SM_B + buf * BUF_SZ;
#pragma unroll
        for (int kc = 0; kc < 4; kc++) {
            uint32_t ah[4], al[4], bh[8], bl[8];
            uint32_t aA = sbA + a_off + kc * 32;
            ldmx4(ah, aA);
            ldmx4(al, aA + 128);
            uint32_t bA = sbB + b_off + kc * 32;
            ldmx4(bh,     bA);
            ldmx4(bh + 4, bA + 16 * PITCHW * 4);
            ldmx4(bl,     bA + 128);
            ldmx4(bl + 4, bA + 16 * PITCHW * 4 + 128);
#pragma unroll
            for (int c = 0; c < 4; c++) mma_bf16(acc[c], ah, bh + 2 * c);   // zhi*whi
#pragma unroll
            for (int c = 0; c < 4; c++) mma_bf16(acc[c], ah, bl + 2 * c);   // zhi*wlo
#pragma unroll
            for (int c = 0; c < 4; c++) mma_bf16(acc[c], al, bh + 2 * c);   // zlo*whi
        }

        if (i < IN_DIM - 1) {
            build_A(i + 1, buf ^ 1);
            CP_WAIT0();
        }
        __syncthreads();
    }

    // ---- epilogue: D[t][o] + bias -> outtile[o][t] (pitch 68, conflict-free) ----
    {
        const int tl0 = 16 * mb + (lane >> 2);
#pragma unroll
        for (int c = 0; c < 4; c++) {
            int o0 = 32 * nb + 8 * c + 2 * (lane & 3);
            outtile[o0 * PITCHW + tl0]           = acc[c][0] + bias_s[o0];
            outtile[(o0 + 1) * PITCHW + tl0]     = acc[c][1] + bias_s[o0 + 1];
            outtile[o0 * PITCHW + tl0 + 8]       = acc[c][2] + bias_s[o0];
            outtile[(o0 + 1) * PITCHW + tl0 + 8] = acc[c][3] + bias_s[o0 + 1];
        }
    }
    __syncthreads();

    // ---- coalesced STG.128: 1024 float4 quads, 4 per thread ----
#pragma unroll
    for (int r2 = 0; r2 < 4; r2++) {
        int u  = tid + r2 * THREADS;                 // 0..1023
        int o  = u >> 4;
        int tq = u & 15;
        float4 v = *(float4*)(outtile + o * PITCHW + 4 * tq);
        *(float4*)(out + (b * OUT_DIM + o) * N_REAL + t0 + 4 * tq) = v;
    }
}

// ---------------- launch ----------------

extern "C" void kernel_launch(void* const* d_in, const int* in_sizes, int n_in,
                              void* d_out, int out_size) {
    const float* x      = (const float*)d_in[0];   // (4, 8, 4096)
    const float* weight = (const float*)d_in[1];   // (64, 8, 64)
    const float* bias   = (const float*)d_in[2];   // (64,)
    const int*   srcIdx = (const int*)d_in[3];     // (4, 4096)
    float*       out    = (float*)d_out;           // (4, 64, 6144)

    static bool attr_done = false;
    if (!attr_done) {
        cudaFuncSetAttribute(conv_mma, cudaFuncAttributeMaxDynamicSharedMemorySize, SMEM_TOTAL);
        attr_done = true;
    }

    wprep<<<(OUT_DIM * IN_DIM * N_WIN + 255) / 256, 256>>>(weight);
    conv_mma<<<BB * NTILES, THREADS, SMEM_TOTAL>>>(x, srcIdx, bias, out);
}

// round 9
// speedup vs baseline: 3.3736x; 1.4286x over previous
#include <cuda_runtime.h>
#include <cuda_bf16.h>
#include <cstdint>

#define BB      4
#define IN_DIM  8
#define OUT_DIM 64
#define N_WIN   64
#define N_SEQ   4096
#define N_REAL  6144

#define T_TILE  64
#define NTILES  (N_REAL / T_TILE)   // 96
#define THREADS 256

// Precomputed B fragment table: exact per-lane mma.sync register values.
// Layout (uint32 words): [i][nb][kc] block of 512 words = 4 slots x (32 lanes x 4 words).
// slot0-1 = bh[0..7], slot2-3 = bl[0..7]. 128KB total.
__device__ __align__(16) uint32_t g_Bf[IN_DIM * 2 * 4 * 512];

// ---------------- helpers ----------------

// pack {lo16: bf16(z0), hi16: bf16(z1)}
__device__ __forceinline__ uint32_t bfpair(float z0, float z1) {
    uint32_t r;
    asm("cvt.rn.bf16x2.f32 %0, %1, %2;" : "=r"(r) : "f"(z1), "f"(z0));
    return r;
}

__device__ __forceinline__ void mma_bf16(float* d, const uint32_t* a, const uint32_t* b) {
    asm volatile(
        "mma.sync.aligned.m16n8k16.row.col.f32.bf16.bf16.f32 "
        "{%0,%1,%2,%3}, {%4,%5,%6,%7}, {%8,%9}, {%0,%1,%2,%3};"
        : "+f"(d[0]), "+f"(d[1]), "+f"(d[2]), "+f"(d[3])
        : "r"(a[0]), "r"(a[1]), "r"(a[2]), "r"(a[3]), "r"(b[0]), "r"(b[1]));
}

// ---------------- weight prep: emit per-lane B fragments (hi/lo split, lag flipped) ----------------
// B per i: B[k][o] = W[o][i][63-k]  (lag axis flipped so A[r][c] = zwin[r+c]).
// m16n8k16 "col" B fragment (PTX ISA): for n8-group c (f = 2c+q):
//   word of lane l = ( B[kk][o], B[kk+1][o] ),  o = 32nb + 8c + l/4, kk = 16kc + 2(l%4) + 8q.

__global__ void wprep_frag(const float* __restrict__ w) {
    int g = blockIdx.x * 256 + threadIdx.x;     // 32768 words
    if (g >= IN_DIM * 2 * 4 * 512) return;
    int lane = g & 31;
    int j    = (g >> 5) & 15;                   // word index within (i,nb,kc): 0..15
    int kc   = (g >> 9) & 3;
    int nb   = (g >> 11) & 1;
    int i    = (g >> 12) & 7;
    int f    = j & 7;                           // fragment index 0..7
    int lopart = j >> 3;                        // 0 = hi words, 1 = lo words
    int c = f >> 1, q = f & 1;
    int o  = 32 * nb + 8 * c + (lane >> 2);
    int kk = 16 * kc + 2 * (lane & 3) + 8 * q;
    float v0 = w[(o * IN_DIM + i) * N_WIN + (63 - kk)];
    float v1 = w[(o * IN_DIM + i) * N_WIN + (62 - kk)];
    __nv_bfloat16 h0 = __float2bfloat16(v0), h1 = __float2bfloat16(v1);
    uint32_t word;
    if (!lopart) word = bfpair(__bfloat162float(h0), __bfloat162float(h1));
    else         word = bfpair(v0 - __bfloat162float(h0), v1 - __bfloat162float(h1));
    int idx = (((i * 2 + nb) * 4 + kc) * 4 + (j >> 2)) * 128 + lane * 4 + (j & 3);
    g_Bf[idx] = word;
}

// ---------------- main kernel ----------------
// SMEM: zpair_hi 8x128 u32 @0 | zpair_lo @4096 | zraw 8x128 f32 @8192 |
//       bias @12288 | outtile 64x68 f32 @12544
#define SM_ZPH  0
#define SM_ZPL  4096
#define SM_ZRAW 8192
#define SM_BIAS 12288
#define SM_OUT  12544
#define PITCHW  68
#define SMEM_TOTAL (SM_OUT + OUT_DIM * PITCHW * 4)   // 29952

__global__ __launch_bounds__(THREADS, 3)
void conv_mma(const float* __restrict__ x, const int* __restrict__ srcIdx,
              const float* __restrict__ bias, float* __restrict__ out) {
    extern __shared__ __align__(16) unsigned char smem[];
    uint32_t* zph_all = (uint32_t*)(smem + SM_ZPH);
    uint32_t* zpl_all = (uint32_t*)(smem + SM_ZPL);
    float*    zraw    = (float*)(smem + SM_ZRAW);
    float*    bias_s  = (float*)(smem + SM_BIAS);
    float*    outtile = (float*)(smem + SM_OUT);

    const int tid  = threadIdx.x;
    const int wid  = tid >> 5;
    const int lane = tid & 31;
    const int b    = blockIdx.x / NTILES;
    const int t0   = (blockIdx.x % NTILES) * T_TILE;

    if (tid < OUT_DIM) bias_s[tid] = bias[tid];
#pragma unroll
    for (int p = 0; p < 4; p++) zraw[tid + p * THREADS] = 0.f;
    __syncthreads();

    // ---- stage z window [t0-63, t0+63] via binary search on sorted-unique sourceIdx ----
    const int* rowp = srcIdx + b * N_SEQ;
    const int tlo = t0 - 63, thi = t0 + 63;
    int lo = 0, hi = N_SEQ;
    while (lo < hi) { int m = (lo + hi) >> 1; if (rowp[m] < tlo) lo = m + 1; else hi = m; }
    const int s_lo = lo;
    hi = N_SEQ;
    while (lo < hi) { int m = (lo + hi) >> 1; if (rowp[m] <= thi) lo = m + 1; else hi = m; }
    const int s_hi = lo;
    for (int s = s_lo + tid; s < s_hi; s += THREADS) {
        int tl = rowp[s] - tlo;                      // [0, 126]
#pragma unroll
        for (int i = 0; i < IN_DIM; i++)
            zraw[i * 128 + tl] = x[(b * IN_DIM + i) * N_SEQ + s];
    }
    __syncthreads();

    // ---- build hi/lo pair tables: zpair[i][k] = pack(z[k], z[k+1]), k = e & 127 (exact) ----
#pragma unroll
    for (int p = 0; p < 4; p++) {
        int e = tid + p * THREADS;                   // 0..1023
        int k = e & 127;                             // row stride 128 -> mask is exact mod
        float z0 = zraw[e];
        float z1 = (k < 127) ? zraw[e + 1] : 0.f;
        uint32_t hp = bfpair(z0, z1);
        float h0 = __uint_as_float(hp << 16);
        float h1 = __uint_as_float(hp & 0xffff0000u);
        zph_all[e] = hp;
        zpl_all[e] = bfpair(z0 - h0, z1 - h1);
    }
    __syncthreads();

    // ---- fragment geometry ----
    const int mb  = wid & 3;                         // m16 tile: t rows [16mb, 16mb+16)
    const int nb  = wid >> 2;                        // n32 half
    const int lg  = lane >> 2;
    const int lp4 = lane & 3;
    const int rA  = 16 * mb + lg;

    float acc[4][4];
#pragma unroll
    for (int c = 0; c < 4; c++)
#pragma unroll
        for (int q = 0; q < 4; q++) acc[c][q] = 0.f;

    // ---- main loop: no barriers, no smem tiles, pure streaming ----
#pragma unroll 2
    for (int i = 0; i < IN_DIM; i++) {
        const uint32_t* zph = zph_all + i * 128;
        const uint32_t* zpl = zpl_all + i * 128;
        const uint4*    bfi = (const uint4*)g_Bf + (i * 2 + nb) * 512 + lane;
#pragma unroll
        for (int kc = 0; kc < 4; kc++) {
            const int cb = 16 * kc + 2 * lp4;
            // Hankel A: A[r][c] = zwin[r+c] -> a1 (row+8) and a2 (col+8) share the same word
            uint32_t ah[4], al[4];
            uint32_t w0h = zph[rA + cb], w8h = zph[rA + cb + 8], w16h = zph[rA + cb + 16];
            uint32_t w0l = zpl[rA + cb], w8l = zpl[rA + cb + 8], w16l = zpl[rA + cb + 16];
            ah[0] = w0h; ah[1] = w8h; ah[2] = w8h; ah[3] = w16h;
            al[0] = w0l; al[1] = w8l; al[2] = w8l; al[3] = w16l;

            const uint4* bp = bfi + kc * 128;
            uint4 s0 = bp[0], s1 = bp[32], s2 = bp[64], s3 = bp[96];
            uint32_t bh[8] = {s0.x, s0.y, s0.z, s0.w, s1.x, s1.y, s1.z, s1.w};
            uint32_t bl[8] = {s2.x, s2.y, s2.z, s2.w, s3.x, s3.y, s3.z, s3.w};

#pragma unroll
            for (int c = 0; c < 4; c++) mma_bf16(acc[c], ah, bh + 2 * c);   // zhi*whi
#pragma unroll
            for (int c = 0; c < 4; c++) mma_bf16(acc[c], ah, bl + 2 * c);   // zhi*wlo
#pragma unroll
            for (int c = 0; c < 4; c++) mma_bf16(acc[c], al, bh + 2 * c);   // zlo*whi
        }
    }

    // ---- epilogue: D[t][o] + bias -> outtile[o][t] (pitch 68) ----
    {
        const int tl0 = rA;
#pragma unroll
        for (int c = 0; c < 4; c++) {
            int o0 = 32 * nb + 8 * c + 2 * lp4;
            outtile[o0 * PITCHW + tl0]           = acc[c][0] + bias_s[o0];
            outtile[(o0 + 1) * PITCHW + tl0]     = acc[c][1] + bias_s[o0 + 1];
            outtile[o0 * PITCHW + tl0 + 8]       = acc[c][2] + bias_s[o0];
            outtile[(o0 + 1) * PITCHW + tl0 + 8] = acc[c][3] + bias_s[o0 + 1];
        }
    }
    __syncthreads();

    // ---- coalesced STG.128: 1024 float4 quads, 4 per thread ----
#pragma unroll
    for (int r2 = 0; r2 < 4; r2++) {
        int u  = tid + r2 * THREADS;                 // 0..1023
        int o  = u >> 4;
        int tq = u & 15;
        float4 v = *(float4*)(outtile + o * PITCHW + 4 * tq);
        *(float4*)(out + (b * OUT_DIM + o) * N_REAL + t0 + 4 * tq) = v;
    }
}

// ---------------- launch ----------------

extern "C" void kernel_launch(void* const* d_in, const int* in_sizes, int n_in,
                              void* d_out, int out_size) {
    const float* x      = (const float*)d_in[0];   // (4, 8, 4096)
    const float* weight = (const float*)d_in[1];   // (64, 8, 64)
    const float* bias   = (const float*)d_in[2];   // (64,)
    const int*   srcIdx = (const int*)d_in[3];     // (4, 4096)
    float*       out    = (float*)d_out;           // (4, 64, 6144)

    static bool attr_done = false;
    if (!attr_done) {
        cudaFuncSetAttribute(conv_mma, cudaFuncAttributeMaxDynamicSharedMemorySize, SMEM_TOTAL);
        attr_done = true;
    }

    wprep_frag<<<(IN_DIM * 2 * 4 * 512 + 255) / 256, 256>>>(weight);
    conv_mma<<<BB * NTILES, THREADS, SMEM_TOTAL>>>(x, srcIdx, bias, out);
}